// round 2
// baseline (speedup 1.0000x reference)
#include <cuda_runtime.h>
#include <cuda_bf16.h>

// EdgeMLP restructured:
//   per-node precompute: a[n] = x[n] @ W1[0:6] + b1   (10 floats)
//                        b[n] = x[n] @ W1[6:12]       (10 floats)
//   per-edge:  h_f = relu(a[src] + b[tgt] + ea  * w1e)
//              h_r = relu(a[tgt] + b[src] + eaT * w1e)
//              out = sigmoid( 0.5*(h_f+h_r) . (W2[:,1]-W2[:,0]) + (b2[1]-b2[0]) )
//
// Node table = 100000 * 20 floats = 8 MB -> resident in L2 (126 MB).
// edge_index is INT32 (JAX x64 disabled downcasts int64 -> int32).

#define N_NODES 100000
#define HID     10

__device__ float g_node[N_NODES * 20];   // [a0..a9, b0..b9] per node
__device__ float g_params[21];           // [0:10)=w1e, [10:20)=w2diff, [20]=b2diff

__global__ void precompute_kernel(const float* __restrict__ x,
                                  const float* __restrict__ W1,
                                  const float* __restrict__ b1,
                                  const float* __restrict__ W2,
                                  const float* __restrict__ b2,
                                  int N)
{
    int n = blockIdx.x * blockDim.x + threadIdx.x;

    if (n == 0) {
        #pragma unroll
        for (int j = 0; j < HID; ++j) {
            g_params[j]      = W1[12 * HID + j];           // edge-attr row of W1
            g_params[10 + j] = W2[j * 2 + 1] - W2[j * 2];  // W2 col diff
        }
        g_params[20] = b2[1] - b2[0];
    }

    if (n >= N) return;

    float xi[6];
    #pragma unroll
    for (int i = 0; i < 6; ++i) xi[i] = x[n * 6 + i];

    float rec[20];
    #pragma unroll
    for (int j = 0; j < HID; ++j) {
        float av = b1[j];
        float bv = 0.0f;
        #pragma unroll
        for (int i = 0; i < 6; ++i) {
            av = fmaf(xi[i], W1[i * HID + j],       av);
            bv = fmaf(xi[i], W1[(6 + i) * HID + j], bv);
        }
        rec[j]      = av;
        rec[10 + j] = bv;
    }

    float4* dst = reinterpret_cast<float4*>(g_node) + (size_t)n * 5;
    #pragma unroll
    for (int k = 0; k < 5; ++k)
        dst[k] = make_float4(rec[4 * k], rec[4 * k + 1], rec[4 * k + 2], rec[4 * k + 3]);
}

__global__ __launch_bounds__(256)
void edge_kernel(const int* __restrict__ ei,        // [2, E] int32
                 const float* __restrict__ ea,
                 const float* __restrict__ eaT,
                 float* __restrict__ out,
                 int E, int N)
{
    int e = blockIdx.x * blockDim.x + threadIdx.x;
    if (e >= E) return;

    int s = ei[e];
    int t = ei[(size_t)E + e];
    // branch-free safety clamp (should be no-ops for valid data)
    s = min(max(s, 0), N - 1);
    t = min(max(t, 0), N - 1);

    float fe  = ea[e];
    float feT = eaT[e];

    const float4* ps = reinterpret_cast<const float4*>(g_node) + (size_t)s * 5;
    const float4* pt = reinterpret_cast<const float4*>(g_node) + (size_t)t * 5;

    float ns[20], nt[20];
    #pragma unroll
    for (int k = 0; k < 5; ++k) {
        float4 vs = ps[k];
        float4 vt = pt[k];
        ns[4 * k + 0] = vs.x; ns[4 * k + 1] = vs.y; ns[4 * k + 2] = vs.z; ns[4 * k + 3] = vs.w;
        nt[4 * k + 0] = vt.x; nt[4 * k + 1] = vt.y; nt[4 * k + 2] = vt.z; nt[4 * k + 3] = vt.w;
    }

    float acc = 0.0f;
    #pragma unroll
    for (int j = 0; j < HID; ++j) {
        float wj  = __ldg(&g_params[j]);
        float w2j = __ldg(&g_params[10 + j]);
        float hf = fmaxf(fmaf(fe,  wj, ns[j] + nt[10 + j]), 0.0f);
        float hr = fmaxf(fmaf(feT, wj, nt[j] + ns[10 + j]), 0.0f);
        acc = fmaf(hf + hr, w2j, acc);
    }

    float d = fmaf(0.5f, acc, __ldg(&g_params[20]));
    out[e] = 1.0f / (1.0f + __expf(-d));
}

extern "C" void kernel_launch(void* const* d_in, const int* in_sizes, int n_in,
                              void* d_out, int out_size)
{
    const float* x   = (const float*)d_in[0];
    const int*   ei  = (const int*)d_in[1];
    const float* ea  = (const float*)d_in[2];
    const float* eaT = (const float*)d_in[3];
    const float* W1  = (const float*)d_in[4];
    const float* b1  = (const float*)d_in[5];
    const float* W2  = (const float*)d_in[6];
    const float* b2  = (const float*)d_in[7];
    float*       out = (float*)d_out;

    int N = in_sizes[0] / 6;
    if (N > N_NODES) N = N_NODES;
    int E = in_sizes[2];   // edge_attr has IN_EDGE=1 element per edge

    precompute_kernel<<<(N + 255) / 256, 256>>>(x, W1, b1, W2, b2, N);
    edge_kernel<<<(E + 255) / 256, 256>>>(ei, ea, eaT, out, E, N);
}

// round 3
// speedup vs baseline: 1.5423x; 1.5423x over previous
#include <cuda_runtime.h>
#include <cuda_fp16.h>

// EdgeMLP restructured:
//   per-node precompute: a[n] = x[n] @ W1[0:6] + b1   (10 floats)
//                        b[n] = x[n] @ W1[6:12]       (10 floats)
//   stored fp16-packed: rec[j] = half2(a_j, b_j), j=0..9, padded to 48 B.
//   per-edge:  h_f = relu(a_s + b_t + ea  * w1e)
//              h_r = relu(a_t + b_s + eaT * w1e)
//              out = sigmoid( 0.5*(h_f+h_r) . (W2[:,1]-W2[:,0]) + (b2[1]-b2[0]) )
//
// Node table = 100000 * 48 B = 4.8 MB -> resident in L2; gathers are
// L1tex-wavefront bound, so the fp16 record halves the LSU work per edge.

#define N_NODES 100000
#define HID     10

__device__ uint4 g_node[N_NODES * 3];    // 48 B per node: 10 half2 + 8 B pad
__device__ float g_params[21];           // [0:10)=w1e, [10:20)=w2diff, [20]=b2diff

__global__ void precompute_kernel(const float* __restrict__ x,
                                  const float* __restrict__ W1,
                                  const float* __restrict__ b1,
                                  const float* __restrict__ W2,
                                  const float* __restrict__ b2,
                                  int N)
{
    int n = blockIdx.x * blockDim.x + threadIdx.x;

    if (n == 0) {
        #pragma unroll
        for (int j = 0; j < HID; ++j) {
            g_params[j]      = W1[12 * HID + j];           // edge-attr row of W1
            g_params[10 + j] = W2[j * 2 + 1] - W2[j * 2];  // W2 col diff
        }
        g_params[20] = b2[1] - b2[0];
    }

    if (n >= N) return;

    float xi[6];
    #pragma unroll
    for (int i = 0; i < 6; ++i) xi[i] = x[n * 6 + i];

    unsigned int packed[12];
    #pragma unroll
    for (int k = 10; k < 12; ++k) packed[k] = 0u;

    #pragma unroll
    for (int j = 0; j < HID; ++j) {
        float av = b1[j];
        float bv = 0.0f;
        #pragma unroll
        for (int i = 0; i < 6; ++i) {
            av = fmaf(xi[i], W1[i * HID + j],       av);
            bv = fmaf(xi[i], W1[(6 + i) * HID + j], bv);
        }
        __half2 h = __floats2half2_rn(av, bv);   // (a_j, b_j)
        packed[j] = *reinterpret_cast<unsigned int*>(&h);
    }

    uint4* dst = g_node + (size_t)n * 3;
    dst[0] = make_uint4(packed[0], packed[1], packed[2],  packed[3]);
    dst[1] = make_uint4(packed[4], packed[5], packed[6],  packed[7]);
    dst[2] = make_uint4(packed[8], packed[9], packed[10], packed[11]);
}

__device__ __forceinline__ float2 unpack_h2(unsigned int u)
{
    __half2 h = *reinterpret_cast<__half2*>(&u);
    return __half22float2(h);
}

__global__ __launch_bounds__(256)
void edge_kernel(const int* __restrict__ ei,        // [2, E] int32
                 const float* __restrict__ ea,
                 const float* __restrict__ eaT,
                 float* __restrict__ out,
                 int E, int N)
{
    int e = blockIdx.x * blockDim.x + threadIdx.x;
    if (e >= E) return;

    int s = ei[e];
    int t = ei[(size_t)E + e];
    s = min(max(s, 0), N - 1);
    t = min(max(t, 0), N - 1);

    float fe  = ea[e];
    float feT = eaT[e];

    const uint4* ps = g_node + (size_t)s * 3;
    const uint4* pt = g_node + (size_t)t * 3;

    uint4 s0 = ps[0], s1 = ps[1], s2 = ps[2];
    uint4 t0 = pt[0], t1 = pt[1], t2 = pt[2];

    unsigned int su[10] = { s0.x, s0.y, s0.z, s0.w, s1.x, s1.y, s1.z, s1.w, s2.x, s2.y };
    unsigned int tu[10] = { t0.x, t0.y, t0.z, t0.w, t1.x, t1.y, t1.z, t1.w, t2.x, t2.y };

    float acc = 0.0f;
    #pragma unroll
    for (int j = 0; j < HID; ++j) {
        float wj  = __ldg(&g_params[j]);
        float w2j = __ldg(&g_params[10 + j]);
        float2 vs = unpack_h2(su[j]);   // (a_s, b_s)
        float2 vt = unpack_h2(tu[j]);   // (a_t, b_t)
        float hf = fmaxf(fmaf(fe,  wj, vs.x + vt.y), 0.0f);
        float hr = fmaxf(fmaf(feT, wj, vt.x + vs.y), 0.0f);
        acc = fmaf(hf + hr, w2j, acc);
    }

    float d = fmaf(0.5f, acc, __ldg(&g_params[20]));
    out[e] = 1.0f / (1.0f + __expf(-d));
}

extern "C" void kernel_launch(void* const* d_in, const int* in_sizes, int n_in,
                              void* d_out, int out_size)
{
    const float* x   = (const float*)d_in[0];
    const int*   ei  = (const int*)d_in[1];
    const float* ea  = (const float*)d_in[2];
    const float* eaT = (const float*)d_in[3];
    const float* W1  = (const float*)d_in[4];
    const float* b1  = (const float*)d_in[5];
    const float* W2  = (const float*)d_in[6];
    const float* b2  = (const float*)d_in[7];
    float*       out = (float*)d_out;

    int N = in_sizes[0] / 6;
    if (N > N_NODES) N = N_NODES;
    int E = in_sizes[2];

    precompute_kernel<<<(N + 255) / 256, 256>>>(x, W1, b1, W2, b2, N);
    edge_kernel<<<(E + 255) / 256, 256>>>(ei, ea, eaT, out, E, N);
}